// round 1
// baseline (speedup 1.0000x reference)
#include <cuda_runtime.h>

// CapsuleConvTranspose2d:
//   input  (2, 64, 32, 32) f32
//   weight (8, 8, 8, 3, 3)  f32  [l, g, m, kh, kw]
//   bias   (8, 8)           f32  [g, m]
//   output (2, 64, 64, 64)  f32  channel = g*8 + m
//
// priors[n,p,q,g,f,kh,kw,m] = sum_l patch[n,f,l,kh,kw,p,q] * weight[l,g,m,2-kh,2-kw]
// patch = input[n, f*8+l, (p+kh-1)/2, (q+kw-1)/2] if (p+kh-1) even & in [0,62], else 0.
// Routing over 72 priors (zeros included in mean + softmax denominator).

__global__ __launch_bounds__(64)
void caps_kernel(const float* __restrict__ x,
                 const float* __restrict__ wt,
                 const float* __restrict__ bs,
                 float* __restrict__ y)
{
    const int pix = blockIdx.x;
    const int q = pix & 63;
    const int p = (pix >> 6) & 63;
    const int n = pix >> 12;
    const int tid = threadIdx.x;
    const int g = tid >> 3;    // out capsule
    const int m = tid & 7;     // out dim

    // Valid kernel taps (structural nonzeros of the transposed conv)
    int khs[2], kws[2];
    int nkh = 0, nkw = 0;
    #pragma unroll
    for (int k = 0; k < 3; k++) {
        int t = p + k - 1;
        if (t >= 0 && t <= 62 && ((t & 1) == 0)) khs[nkh++] = k;
        int u = q + k - 1;
        if (u >= 0 && u <= 62 && ((u & 1) == 0)) kws[nkw++] = k;
    }
    const int ntap = nkh * nkw;      // 1, 2, or 4
    const int nv = 8 * ntap;         // nonzero priors per (g): 8, 16, 32

    __shared__ float s_x[4][64];     // [tap][channel]
    __shared__ float s_pri[8][32][9];// [g][prior][m], pitch 9 avoids bank conflicts
    __shared__ float s_e[8][32];     // softmax numerators

    // ---- Stage input patch values (<= 4 spatial positions x 64 channels) ----
    const int nload = ntap << 6;
    for (int idx = tid; idx < nload; idx += 64) {
        int pos = idx >> 6;
        int c = idx & 63;
        int a = pos / nkw;
        int b = pos - a * nkw;
        int i = (p + khs[a] - 1) >> 1;
        int j = (q + kws[b] - 1) >> 1;
        s_x[pos][c] = x[((n * 64 + c) * 32 + i) * 32 + j];
    }
    __syncthreads();

    // ---- Per-thread weights: wr[tap][l] = weight[l][g][m][2-kh][2-kw] ----
    float wr[4][8];
    #pragma unroll
    for (int t = 0; t < 4; t++) {
        if (t < ntap) {
            int a = t / nkw;
            int b = t - a * nkw;
            int kh2 = 2 - khs[a];
            int kw2 = 2 - kws[b];
            #pragma unroll
            for (int l = 0; l < 8; l++)
                wr[t][l] = wt[(((l * 8 + g) * 8 + m) * 3 + kh2) * 3 + kw2];
        }
    }

    // ---- Priors: 8x8 matvec per (f, tap) ----
    #pragma unroll
    for (int f = 0; f < 8; f++) {
        #pragma unroll
        for (int t = 0; t < 4; t++) {
            if (t < ntap) {
                float acc = 0.f;
                #pragma unroll
                for (int l = 0; l < 8; l++)
                    acc += s_x[t][f * 8 + l] * wr[t][l];
                s_pri[g][f * ntap + t][m] = acc;
            }
        }
    }
    __syncwarp();

    // ---- Routing init: mean over all 72 (zeros included in divisor) ----
    float o = 0.f;
    for (int i = 0; i < nv; i++) o += s_pri[g][i][m];
    o *= (1.0f / 72.0f);

    const unsigned FULL = 0xffffffffu;
    const int cnt = nv >> 3;         // priors owned per thread (1,2,4)
    const float nzeros = (float)(72 - nv);

    #pragma unroll
    for (int it = 0; it < 3; it++) {
        // norm over m (8-lane reduce)
        float sn = o * o;
        sn += __shfl_xor_sync(FULL, sn, 1, 8);
        sn += __shfl_xor_sync(FULL, sn, 2, 8);
        sn += __shfl_xor_sync(FULL, sn, 4, 8);
        float on = o / fmaxf(sqrtf(sn), 1e-12f);

        // broadcast full out_n vector to registers
        float onv[8];
        #pragma unroll
        for (int j = 0; j < 8; j++) onv[j] = __shfl_sync(FULL, on, j, 8);

        // logits for this thread's prior subset (i = m, m+8, ...)
        float lg[4];
        float lmax = 0.0f;   // zero-priors have logit exactly 0 and always exist
        for (int k = 0; k < cnt; k++) {
            int i = m + 8 * k;
            float s = 0.f;
            #pragma unroll
            for (int j = 0; j < 8; j++) s += s_pri[g][i][j] * onv[j];
            lg[k] = s;
            lmax = fmaxf(lmax, s);
        }
        lmax = fmaxf(lmax, __shfl_xor_sync(FULL, lmax, 1, 8));
        lmax = fmaxf(lmax, __shfl_xor_sync(FULL, lmax, 2, 8));
        lmax = fmaxf(lmax, __shfl_xor_sync(FULL, lmax, 4, 8));

        float z = 0.f;
        for (int k = 0; k < cnt; k++) {
            float e = expf(lg[k] - lmax);
            s_e[g][m + 8 * k] = e;
            z += e;
        }
        z += __shfl_xor_sync(FULL, z, 1, 8);
        z += __shfl_xor_sync(FULL, z, 2, 8);
        z += __shfl_xor_sync(FULL, z, 4, 8);
        z += nzeros * expf(-lmax);   // zero-priors' softmax denominator share
        __syncwarp();

        // out = sum probs_i * priors_i  (zero priors contribute nothing)
        float acc = 0.f;
        for (int i = 0; i < nv; i++) acc += s_e[g][i] * s_pri[g][i][m];
        o = acc / z;
        __syncwarp();
    }

    // ---- squash + bias ----
    float sn = o * o;
    sn += __shfl_xor_sync(FULL, sn, 1, 8);
    sn += __shfl_xor_sync(FULL, sn, 2, 8);
    sn += __shfl_xor_sync(FULL, sn, 4, 8);
    o = o * (sn / ((1.0f + sn) * sqrtf(sn + 1e-12f)));
    o += bs[g * 8 + m];

    y[((n * 64 + g * 8 + m) * 64 + p) * 64 + q] = o;
}

extern "C" void kernel_launch(void* const* d_in, const int* in_sizes, int n_in,
                              void* d_out, int out_size) {
    const float* x  = (const float*)d_in[0];
    const float* wt = (const float*)d_in[1];
    const float* bs = (const float*)d_in[2];
    float* y = (float*)d_out;
    caps_kernel<<<2 * 64 * 64, 64>>>(x, wt, bs, y);
}

// round 2
// speedup vs baseline: 1.9761x; 1.9761x over previous
#include <cuda_runtime.h>

// CapsuleConvTranspose2d:
//   input  (2, 64, 32, 32) f32
//   weight (8, 8, 8, 3, 3)  f32  [l, g, m, kh, kw]
//   bias   (8, 8)           f32  [g, m]
//   output (2, 64, 64, 64)  f32  channel = g*8 + m
//
// Transposed-conv structure: patch value is input[n,c,(p+kh-1)/2,(q+kw-1)/2]
// iff (p+kh-1) even and in [0,62]; else exactly 0. So nv = 8*ntap nonzero
// priors per out-capsule, ntap in {1,2,4}. Zero priors still feed the softmax
// denominator (exp(0-lmax) each) and the initial mean divisor (72).
//
// Thread map: 64 threads per output pixel; g = tid>>3 (out cap), r = tid&7.
// Since ntap | 8, lane r owns priors i = r + 8k which all share tap t = r%ntap.
// Each lane keeps its <=4 full 8-dim priors in registers; routing is entirely
// register + shuffle work (no shared memory, no barriers).

__global__ __launch_bounds__(64)
void caps_kernel(const float* __restrict__ x,
                 const float* __restrict__ wt,
                 const float* __restrict__ bs,
                 float* __restrict__ y)
{
    const int pix = blockIdx.x;
    const int q = pix & 63;
    const int p = (pix >> 6) & 63;
    const int n = pix >> 12;
    const int tid = threadIdx.x;
    const int g = tid >> 3;    // out capsule
    const int r = tid & 7;     // lane within capsule group

    // Valid kernel taps (structural nonzeros of the transposed conv)
    int khs[2], kws[2];
    int nkh = 0, nkw = 0;
    #pragma unroll
    for (int k = 0; k < 3; k++) {
        int tt = p + k - 1;
        if (tt >= 0 && tt <= 62 && !(tt & 1)) khs[nkh++] = k;
        int uu = q + k - 1;
        if (uu >= 0 && uu <= 62 && !(uu & 1)) kws[nkw++] = k;
    }
    const int ntap = nkh * nkw;      // 1, 2, or 4
    const int nv = ntap << 3;        // nonzero priors per capsule

    __shared__ float s_x[4][64];     // [tap][channel]

    // ---- Stage input patch values (ntap spatial positions x 64 channels) ----
    const int nload = ntap << 6;
    for (int idx = tid; idx < nload; idx += 64) {
        int pos = idx >> 6;
        int c = idx & 63;
        int a = pos / nkw;
        int b = pos - a * nkw;
        int i = (p + khs[a] - 1) >> 1;
        int j = (q + kws[b] - 1) >> 1;
        s_x[pos][c] = x[((n * 64 + c) * 32 + i) * 32 + j];
    }
    __syncthreads();

    // ---- This lane's tap & prior set: i = r + 8k, t = r % ntap (const) ----
    const int t   = r % ntap;
    const int a   = t / nkw;
    const int b   = t - a * nkw;
    const int woff = (2 - khs[a]) * 3 + (2 - kws[b]);   // flipped kernel offset
    const int cnt  = ntap;                               // priors owned (<=4)
    const int fstep = 8 / ntap;
    const int f0    = r / ntap;

    // ---- Compute owned priors fully in registers ----
    float pri[4][8];
    #pragma unroll
    for (int k = 0; k < 4; k++)
        #pragma unroll
        for (int m = 0; m < 8; m++) pri[k][m] = 0.f;

    #pragma unroll
    for (int l = 0; l < 8; l++) {
        float wv[8];
        #pragma unroll
        for (int m = 0; m < 8; m++)
            wv[m] = __ldg(&wt[((l * 8 + g) * 8 + m) * 9 + woff]);
        #pragma unroll
        for (int k = 0; k < 4; k++) {
            if (k < cnt) {
                float xv = s_x[t][(f0 + k * fstep) * 8 + l];
                #pragma unroll
                for (int m = 0; m < 8; m++)
                    pri[k][m] = fmaf(xv, wv[m], pri[k][m]);
            }
        }
    }

    const unsigned FULL = 0xffffffffu;

    // ---- Routing init: mean over all 72 (zeros included in divisor) ----
    float o[8];
    #pragma unroll
    for (int m = 0; m < 8; m++) {
        float s = 0.f;
        #pragma unroll
        for (int k = 0; k < 4; k++)
            if (k < cnt) s += pri[k][m];
        o[m] = s;
    }
    #pragma unroll
    for (int d = 1; d < 8; d <<= 1)
        #pragma unroll
        for (int m = 0; m < 8; m++)
            o[m] += __shfl_xor_sync(FULL, o[m], d, 8);
    #pragma unroll
    for (int m = 0; m < 8; m++) o[m] *= (1.0f / 72.0f);

    const float nzeros = (float)(72 - nv);

    #pragma unroll
    for (int it = 0; it < 3; it++) {
        // ||out|| (full vector resident in every lane -> pure register math)
        float sn = 0.f;
        #pragma unroll
        for (int m = 0; m < 8; m++) sn = fmaf(o[m], o[m], sn);
        float inv = 1.0f / fmaxf(sqrtf(sn), 1e-12f);

        // logits for owned priors (zero priors have logit exactly 0)
        float lg[4];
        float lmax = 0.0f;
        #pragma unroll
        for (int k = 0; k < 4; k++) {
            if (k < cnt) {
                float s = 0.f;
                #pragma unroll
                for (int m = 0; m < 8; m++) s = fmaf(pri[k][m], o[m], s);
                s *= inv;
                lg[k] = s;
                lmax = fmaxf(lmax, s);
            }
        }
        lmax = fmaxf(lmax, __shfl_xor_sync(FULL, lmax, 1, 8));
        lmax = fmaxf(lmax, __shfl_xor_sync(FULL, lmax, 2, 8));
        lmax = fmaxf(lmax, __shfl_xor_sync(FULL, lmax, 4, 8));

        float e[4];
        float z = 0.f;
        #pragma unroll
        for (int k = 0; k < 4; k++) {
            if (k < cnt) {
                e[k] = __expf(lg[k] - lmax);
                z += e[k];
            }
        }
        z += __shfl_xor_sync(FULL, z, 1, 8);
        z += __shfl_xor_sync(FULL, z, 2, 8);
        z += __shfl_xor_sync(FULL, z, 4, 8);
        z += nzeros * __expf(-lmax);   // zero-priors' denominator share

        // out = sum_i prob_i * prior_i
        float acc[8];
        #pragma unroll
        for (int m = 0; m < 8; m++) acc[m] = 0.f;
        #pragma unroll
        for (int k = 0; k < 4; k++) {
            if (k < cnt) {
                #pragma unroll
                for (int m = 0; m < 8; m++)
                    acc[m] = fmaf(e[k], pri[k][m], acc[m]);
            }
        }
        #pragma unroll
        for (int d = 1; d < 8; d <<= 1)
            #pragma unroll
            for (int m = 0; m < 8; m++)
                acc[m] += __shfl_xor_sync(FULL, acc[m], d, 8);

        float rz = 1.0f / z;
        #pragma unroll
        for (int m = 0; m < 8; m++) o[m] = acc[m] * rz;
    }

    // ---- squash + bias (redundant across 8 lanes; each writes its m = r) ----
    float sn = 0.f;
    #pragma unroll
    for (int m = 0; m < 8; m++) sn = fmaf(o[m], o[m], sn);
    float scale = sn / ((1.0f + sn) * sqrtf(sn + 1e-12f));
    float val = o[r] * scale + bs[g * 8 + r];

    y[((n * 64 + g * 8 + r) * 64 + p) * 64 + q] = val;
}

extern "C" void kernel_launch(void* const* d_in, const int* in_sizes, int n_in,
                              void* d_out, int out_size) {
    const float* x  = (const float*)d_in[0];
    const float* wt = (const float*)d_in[1];
    const float* bs = (const float*)d_in[2];
    float* y = (float*)d_out;
    caps_kernel<<<2 * 64 * 64, 64>>>(x, wt, bs, y);
}